// round 3
// baseline (speedup 1.0000x reference)
#include <cuda_runtime.h>
#include <math.h>

#define NB 16
#define PP 1024

static __constant__ const float dummy_unused = 0.f;

static constexpr float EPSV   = 0.001f;
static constexpr float KLOG   = 1442.6950408889634f;   // 1000 / ln(2)
static constexpr float NKLOG  = -1442.6950408889634f;
static constexpr float EPSLN2 = 6.93147180559945e-4f;  // EPS * ln(2)
static constexpr float LGEPS  = 1e-8f;

__device__ float g_u[NB * PP];
__device__ float g_v[NB * PP];
__device__ float g_part[NB * 64];
__device__ float g_cost[NB];

__device__ __forceinline__ float ex2f(float x) {
    float y; asm("ex2.approx.ftz.f32 %0, %1;" : "=f"(y) : "f"(x)); return y;
}
__device__ __forceinline__ float lg2f(float x) {
    float y; asm("lg2.approx.ftz.f32 %0, %1;" : "=f"(y) : "f"(x)); return y;
}

// Online logsumexp (base 2) update with a SINGLE ex2 per element:
// e = 2^{-|d|} serves both the "rescale old sum" and "add new term" branches.
__device__ __forceinline__ void upd(float& m, float& s, float x) {
    float d = x - m;
    float e = ex2f(-fabsf(d));
    if (d > 0.f) { s = fmaf(s, e, 1.0f); m = x; }
    else         { s = s + e; }
}

// Combine two (max, sum) partials.
__device__ __forceinline__ void comb(float& m, float& s, float m2, float s2) {
    float M = fmaxf(m, m2);
    s = fmaf(s, ex2f(m - M), s2 * ex2f(m2 - M));
    m = M;
}

__global__ void __launch_bounds__(256) init_k() {
    int t = blockIdx.x * blockDim.x + threadIdx.x;
    if (t < NB * PP) g_u[t] = 1.0f;
}

// ---------------------------------------------------------------------------
// Column pass: v_j = EPS*log(nu_j+1e-8) - EPS*LSE_i[(u_i - C_ij)/EPS]
// grid (16, 16): x = 64-column block, y = batch. block = 256 threads.
// thread: 2 adjacent columns (float2 loads), 1/8 of the rows (q = tid>>5).
// ---------------------------------------------------------------------------
__global__ void __launch_bounds__(256) colpass(const float* __restrict__ C,
                                               const float* __restrict__ nu) {
    const int n = blockIdx.y, jb = blockIdx.x;
    __shared__ float us[PP];
    __shared__ float pm[8 * 64];
    __shared__ float ps[8 * 64];
    const int tid = threadIdx.x;

    for (int k = tid; k < PP; k += 256) us[k] = g_u[n * PP + k] * KLOG;
    __syncthreads();

    const int cp = (tid & 31) * 2;   // column pair within the 64-col block
    const int q  = tid >> 5;         // row quarter-of-eight: 128 rows each
    const int j0 = jb * 64 + cp;
    const float* Cp = C + ((size_t)n << 20) + (size_t)(q * 128) * PP + j0;
    const float* up = us + q * 128;

    float m0 = -1e30f, s0 = 0.f, m1 = -1e30f, s1 = 0.f;
#pragma unroll 8
    for (int r = 0; r < 128; ++r) {
        float2 c = *(const float2*)(Cp + (size_t)r * PP);
        float uu = up[r];
        upd(m0, s0, fmaf(c.x, NKLOG, uu));
        upd(m1, s1, fmaf(c.y, NKLOG, uu));
    }
    pm[q * 64 + cp]     = m0;  ps[q * 64 + cp]     = s0;
    pm[q * 64 + cp + 1] = m1;  ps[q * 64 + cp + 1] = s1;
    __syncthreads();

    if (tid < 64) {
        float m = pm[tid], s = ps[tid];
#pragma unroll
        for (int k = 1; k < 8; ++k) comb(m, s, pm[k * 64 + tid], ps[k * 64 + tid]);
        int j = jb * 64 + tid;
        float lse2 = m + lg2f(s);
        g_v[n * PP + j] = EPSV * logf(nu[n * PP + j] + LGEPS) - EPSLN2 * lse2;
    }
}

// ---------------------------------------------------------------------------
// Row pass: u_i = EPS*log(mu_i+1e-8) - EPS*LSE_j[(v_j - C_ij)/EPS]
// grid (16, 16): x = 64-row block, y = batch. 8 warps, each warp 8 rows.
// ---------------------------------------------------------------------------
__global__ void __launch_bounds__(256) rowpass(const float* __restrict__ C,
                                               const float* __restrict__ mu) {
    const int n = blockIdx.y, ib = blockIdx.x;
    __shared__ float vs[PP];
    const int tid = threadIdx.x;
    for (int k = tid; k < PP; k += 256) vs[k] = g_v[n * PP + k] * KLOG;
    __syncthreads();

    const int w = tid >> 5, l = tid & 31;
    const float2* vs2 = (const float2*)vs;

    for (int rr = 0; rr < 8; ++rr) {
        const int i = ib * 64 + w * 8 + rr;
        const float2* Cp = (const float2*)(C + ((size_t)n << 20) + (size_t)i * PP);
        float m0 = -1e30f, s0 = 0.f, m1 = -1e30f, s1 = 0.f;
#pragma unroll
        for (int c = 0; c < 16; c += 2) {
            float2 a  = Cp[c * 32 + l];
            float2 b  = Cp[(c + 1) * 32 + l];
            float2 v0 = vs2[c * 32 + l];
            float2 v1 = vs2[(c + 1) * 32 + l];
            upd(m0, s0, fmaf(a.x, NKLOG, v0.x));
            upd(m1, s1, fmaf(a.y, NKLOG, v0.y));
            upd(m0, s0, fmaf(b.x, NKLOG, v1.x));
            upd(m1, s1, fmaf(b.y, NKLOG, v1.y));
        }
        comb(m0, s0, m1, s1);
#pragma unroll
        for (int off = 16; off; off >>= 1) {
            float mo = __shfl_xor_sync(0xFFFFFFFFu, m0, off);
            float so = __shfl_xor_sync(0xFFFFFFFFu, s0, off);
            comb(m0, s0, mo, so);
        }
        if (l == 0) {
            float lse2 = m0 + lg2f(s0);
            g_u[n * PP + i] = EPSV * logf(mu[n * PP + i] + LGEPS) - EPSLN2 * lse2;
        }
    }
}

// ---------------------------------------------------------------------------
// Final: pi = 2^{(u_i + v_j - C_ij)*K}; per-block partial sums of pi*C.
// grid (64, 16): x = 16-row block, y = batch.
// ---------------------------------------------------------------------------
__global__ void __launch_bounds__(256) finalpass(const float* __restrict__ C,
                                                 float* __restrict__ pi) {
    const int n = blockIdx.y, ib = blockIdx.x;
    __shared__ float vs[PP];
    __shared__ float usr[16];
    __shared__ float red[256];
    const int tid = threadIdx.x;
    for (int k = tid; k < PP; k += 256) vs[k] = g_v[n * PP + k] * KLOG;
    if (tid < 16) usr[tid] = g_u[n * PP + ib * 16 + tid] * KLOG;
    __syncthreads();

    const float4* Cb = (const float4*)(C + ((size_t)n << 20) + (size_t)ib * 16 * PP);
    float4* Pb = pi ? (float4*)(pi + ((size_t)n << 20) + (size_t)ib * 16 * PP) : nullptr;
    const float4* vs4 = (const float4*)vs;

    float acc = 0.f;
#pragma unroll 4
    for (int e = tid; e < 4096; e += 256) {
        int row = e >> 8;          // 256 float4 per row
        int c4  = e & 255;
        float uK = usr[row];
        float4 c = Cb[e];
        float4 vv = vs4[c4];
        float p0 = ex2f(fmaf(c.x, NKLOG, uK + vv.x));
        float p1 = ex2f(fmaf(c.y, NKLOG, uK + vv.y));
        float p2 = ex2f(fmaf(c.z, NKLOG, uK + vv.z));
        float p3 = ex2f(fmaf(c.w, NKLOG, uK + vv.w));
        acc = fmaf(p0, c.x, acc);
        acc = fmaf(p1, c.y, acc);
        acc = fmaf(p2, c.z, acc);
        acc = fmaf(p3, c.w, acc);
        if (Pb) { float4 o = make_float4(p0, p1, p2, p3); Pb[e] = o; }
    }

    red[tid] = acc;
    __syncthreads();
#pragma unroll
    for (int st = 128; st; st >>= 1) {
        if (tid < st) red[tid] += red[tid + st];
        __syncthreads();
    }
    if (tid == 0) g_part[n * 64 + ib] = red[0];
}

// Deterministic final reduction of the 64 block partials per batch.
__global__ void costred(float* __restrict__ cost) {
    int n = threadIdx.x;
    if (n < NB) {
        float s = 0.f;
#pragma unroll
        for (int k = 0; k < 64; ++k) s += g_part[n * 64 + k];
        if (cost) cost[n] = s;
        else      g_cost[n] = s;
    }
}

extern "C" void kernel_launch(void* const* d_in, const int* in_sizes, int n_in,
                              void* d_out, int out_size) {
    // Identify C as the largest input; remaining two are mu, nu in order.
    int ci = 0;
    for (int k = 1; k < n_in; ++k) if (in_sizes[k] > in_sizes[ci]) ci = k;
    const float* in2[2]; int w = 0;
    for (int k = 0; k < n_in && w < 2; ++k) if (k != ci) in2[w++] = (const float*)d_in[k];
    const float* mu = in2[0];
    const float* nu = in2[1];
    const float* C  = (const float*)d_in[ci];

    float* out = (float*)d_out;
    float* cost = nullptr;
    float* pi   = nullptr;
    const int NPI = NB * PP * PP;
    if (out_size >= NPI + NB)      { cost = out;    pi = out + NB; }
    else if (out_size == NPI)      { cost = nullptr; pi = out; }
    else                            { cost = out;    pi = nullptr; }

    init_k<<<(NB * PP + 255) / 256, 256>>>();

    dim3 grid(16, 16);
    for (int it = 0; it < 100; ++it) {
        colpass<<<grid, 256>>>(C, nu);
        rowpass<<<grid, 256>>>(C, mu);
    }

    finalpass<<<dim3(64, 16), 256>>>(C, pi);
    costred<<<1, 32>>>(cost);
}

// round 7
// speedup vs baseline: 1.3608x; 1.3608x over previous
#include <cuda_runtime.h>
#include <math.h>

#define NB 16
#define PP 1024

static constexpr float KLOG   = 1442.6950408889634f;   // 1/(EPS*ln2) = 1000/ln2
static constexpr float NKLOG  = -1442.6950408889634f;
static constexpr float LGEPS  = 1e-8f;

// Scratch (allocation-free: __device__ globals)
__device__ float g_logmu2[NB * PP];   // log2(mu + 1e-8)
__device__ float g_lognu2[NB * PP];   // log2(nu + 1e-8)
__device__ float g_cpm[NB * 4 * PP];  // column-LSE partials (m) [n][rowchunk][j]
__device__ float g_cps[NB * 4 * PP];  // column-LSE partials (s)
__device__ float g_rpm[NB * 4 * PP];  // row-LSE partials (m)   [n][colchunk][i]
__device__ float g_rps[NB * 4 * PP];  // row-LSE partials (s)
__device__ float g_part[NB * 64];
__device__ float g_cost[NB];

__device__ __forceinline__ float ex2f(float x) {
    float y; asm("ex2.approx.ftz.f32 %0, %1;" : "=f"(y) : "f"(x)); return y;
}
__device__ __forceinline__ float lg2f(float x) {
    float y; asm("lg2.approx.ftz.f32 %0, %1;" : "=f"(y) : "f"(x)); return y;
}

// Online base-2 LSE update, 1 ex2/element.
// m chain: FMNMX (4 cyc). s chain: FSEL of two 4-cyc producers; ex2 off-path.
__device__ __forceinline__ void upd(float& m, float& s, float x) {
    float d    = x - m;
    float e    = ex2f(-fabsf(d));
    float sa   = fmaf(s, e, 1.0f);   // if x is new max
    float sb   = s + e;              // if x <= m
    s = (d > 0.f) ? sa : sb;
    m = fmaxf(m, x);
}

// Combine two (offset, sum) partial representations. Exact for any offsets.
__device__ __forceinline__ void comb(float& m, float& s, float m2, float s2) {
    float M = fmaxf(m, m2);
    s = fmaf(s, ex2f(m - M), s2 * ex2f(m2 - M));
    m = M;
}

__global__ void __launch_bounds__(256) init_k(const float* __restrict__ mu,
                                              const float* __restrict__ nu) {
    int t = blockIdx.x * blockDim.x + threadIdx.x;
    if (t < NB * PP) {
        g_logmu2[t] = log2f(mu[t] + LGEPS);
        g_lognu2[t] = log2f(nu[t] + LGEPS);
    }
}

// ---------------------------------------------------------------------------
// Column pass (v update). grid (64, 16): x = cb(16 col-blocks of 64) |
// rc(4 row-chunks of 256) packed; y = batch. 256 threads.
// Prologue: build uK for this row chunk from rowpass partials (or u=1 if FIRST).
// Main: thread = 16 rows x 4 cols (float4), 4 independent LSE chains.
// Epilogue: reduce 16 row-group partials per column, write chunk partials.
// ---------------------------------------------------------------------------
template <bool FIRST>
__global__ void __launch_bounds__(256) colpass(const float* __restrict__ C) {
    const int n  = blockIdx.y;
    const int cb = blockIdx.x & 15;
    const int rc = blockIdx.x >> 4;
    __shared__ float us[256];
    __shared__ float pm[16 * 64];
    __shared__ float ps[16 * 64];
    const int tid = threadIdx.x;

    {   // uK for rows rc*256 .. rc*256+255
        const int i = rc * 256 + tid;
        float uK;
        if (FIRST) {
            uK = KLOG;  // u = 1
        } else {
            const float* pmr = g_rpm + n * 4 * PP;
            const float* psr = g_rps + n * 4 * PP;
            float m = pmr[i], s = psr[i];
            comb(m, s, pmr[PP + i],     psr[PP + i]);
            comb(m, s, pmr[2 * PP + i], psr[2 * PP + i]);
            comb(m, s, pmr[3 * PP + i], psr[3 * PP + i]);
            uK = g_logmu2[n * PP + i] - (m + lg2f(s));
        }
        us[tid] = uK;
    }
    __syncthreads();

    const int cg = tid & 15;   // column group (4 cols each)
    const int rg = tid >> 4;   // row group (16 rows each)
    const float4* Cp = (const float4*)(C + ((size_t)n << 20)
                       + (size_t)(rc * 256 + rg * 16) * PP) + (cb * 16 + cg);
    const float* up = us + rg * 16;

    float m0 = -1e30f, s0 = 0.f, m1 = -1e30f, s1 = 0.f;
    float m2 = -1e30f, s2 = 0.f, m3 = -1e30f, s3 = 0.f;
#pragma unroll
    for (int r = 0; r < 16; ++r) {
        float4 c = Cp[r * (PP / 4)];
        float uu = up[r];
        upd(m0, s0, fmaf(c.x, NKLOG, uu));
        upd(m1, s1, fmaf(c.y, NKLOG, uu));
        upd(m2, s2, fmaf(c.z, NKLOG, uu));
        upd(m3, s3, fmaf(c.w, NKLOG, uu));
    }
    {
        const int col = cg * 4;
        *(float4*)(pm + rg * 64 + col) = make_float4(m0, m1, m2, m3);
        *(float4*)(ps + rg * 64 + col) = make_float4(s0, s1, s2, s3);
    }
    __syncthreads();

    if (tid < 64) {
        float m = pm[tid], s = ps[tid];
#pragma unroll
        for (int k = 1; k < 16; ++k) comb(m, s, pm[k * 64 + tid], ps[k * 64 + tid]);
        const int o = (n * 4 + rc) * PP + cb * 64 + tid;
        g_cpm[o] = m;
        g_cps[o] = s;
    }
}

// ---------------------------------------------------------------------------
// Row pass (u update). grid (64, 16): x = rb(16 row-blocks of 64) |
// cc(4 col-chunks of 256); y = batch. 256 threads, 8 warps x 8 rows each.
// Prologue: build vK for this column chunk from colpass partials.
// Main: per row, lane handles 8 cols via 2 float4 with 2 chains; per-(row,lane)
// partial to padded smem; fixed-order serial combine by 64 threads.
// ---------------------------------------------------------------------------
__global__ void __launch_bounds__(256) rowpass(const float* __restrict__ C) {
    const int n  = blockIdx.y;
    const int rb = blockIdx.x & 15;
    const int cc = blockIdx.x >> 4;
    __shared__ float vs[256];
    __shared__ float pm[64 * 33];
    __shared__ float ps[64 * 33];
    const int tid = threadIdx.x;

    {   // vK for cols cc*256 .. cc*256+255
        const int j = cc * 256 + tid;
        const float* pmc = g_cpm + n * 4 * PP;
        const float* psc = g_cps + n * 4 * PP;
        float m = pmc[j], s = psc[j];
        comb(m, s, pmc[PP + j],     psc[PP + j]);
        comb(m, s, pmc[2 * PP + j], psc[2 * PP + j]);
        comb(m, s, pmc[3 * PP + j], psc[3 * PP + j]);
        vs[tid] = g_lognu2[n * PP + j] - (m + lg2f(s));
    }
    __syncthreads();

    const int w = tid >> 5, l = tid & 31;
    const float4* vs4 = (const float4*)vs;
    const float4 v0 = vs4[l];
    const float4 v1 = vs4[l + 32];

#pragma unroll 2
    for (int r = 0; r < 8; ++r) {
        const int i = rb * 64 + w * 8 + r;
        const float4* Cp = (const float4*)(C + ((size_t)n << 20)
                           + (size_t)i * PP + cc * 256);
        float4 a = Cp[l];
        float4 b = Cp[l + 32];
        float m0 = -1e30f, s0 = 0.f, m1 = -1e30f, s1 = 0.f;
        upd(m0, s0, fmaf(a.x, NKLOG, v0.x));
        upd(m1, s1, fmaf(a.y, NKLOG, v0.y));
        upd(m0, s0, fmaf(a.z, NKLOG, v0.z));
        upd(m1, s1, fmaf(a.w, NKLOG, v0.w));
        upd(m0, s0, fmaf(b.x, NKLOG, v1.x));
        upd(m1, s1, fmaf(b.y, NKLOG, v1.y));
        upd(m0, s0, fmaf(b.z, NKLOG, v1.z));
        upd(m1, s1, fmaf(b.w, NKLOG, v1.w));
        comb(m0, s0, m1, s1);
        const int row = w * 8 + r;
        pm[row * 33 + l] = m0;
        ps[row * 33 + l] = s0;
    }
    __syncthreads();

    if (tid < 64) {
        float m = pm[tid * 33], s = ps[tid * 33];
#pragma unroll
        for (int k = 1; k < 32; ++k) comb(m, s, pm[tid * 33 + k], ps[tid * 33 + k]);
        const int o = (n * 4 + cc) * PP + rb * 64 + tid;
        g_rpm[o] = m;
        g_rps[o] = s;
    }
}

// ---------------------------------------------------------------------------
// Final: combine partials into final uK, vK; pi = 2^(uK + vK - C*K);
// per-block deterministic partial sums of pi*C. grid (64, 16).
// ---------------------------------------------------------------------------
__global__ void __launch_bounds__(256) finalpass(const float* __restrict__ C,
                                                 float* __restrict__ pi) {
    const int n = blockIdx.y, ib = blockIdx.x;
    __shared__ float vsK[PP];
    __shared__ float usr[16];
    __shared__ float red[256];
    const int tid = threadIdx.x;

    for (int j = tid; j < PP; j += 256) {
        const float* pmc = g_cpm + n * 4 * PP;
        const float* psc = g_cps + n * 4 * PP;
        float m = pmc[j], s = psc[j];
        comb(m, s, pmc[PP + j],     psc[PP + j]);
        comb(m, s, pmc[2 * PP + j], psc[2 * PP + j]);
        comb(m, s, pmc[3 * PP + j], psc[3 * PP + j]);
        vsK[j] = g_lognu2[n * PP + j] - (m + lg2f(s));
    }
    if (tid < 16) {
        const int i = ib * 16 + tid;
        const float* pmr = g_rpm + n * 4 * PP;
        const float* psr = g_rps + n * 4 * PP;
        float m = pmr[i], s = psr[i];
        comb(m, s, pmr[PP + i],     psr[PP + i]);
        comb(m, s, pmr[2 * PP + i], psr[2 * PP + i]);
        comb(m, s, pmr[3 * PP + i], psr[3 * PP + i]);
        usr[tid] = g_logmu2[n * PP + i] - (m + lg2f(s));
    }
    __syncthreads();

    const float4* Cb = (const float4*)(C + ((size_t)n << 20) + (size_t)ib * 16 * PP);
    float4* Pb = pi ? (float4*)(pi + ((size_t)n << 20) + (size_t)ib * 16 * PP) : nullptr;
    const float4* vs4 = (const float4*)vsK;

    float acc = 0.f;
#pragma unroll 4
    for (int e = tid; e < 4096; e += 256) {
        int row = e >> 8;
        int c4  = e & 255;
        float uK = usr[row];
        float4 c  = Cb[e];
        float4 vv = vs4[c4];
        float p0 = ex2f(fmaf(c.x, NKLOG, uK + vv.x));
        float p1 = ex2f(fmaf(c.y, NKLOG, uK + vv.y));
        float p2 = ex2f(fmaf(c.z, NKLOG, uK + vv.z));
        float p3 = ex2f(fmaf(c.w, NKLOG, uK + vv.w));
        acc = fmaf(p0, c.x, acc);
        acc = fmaf(p1, c.y, acc);
        acc = fmaf(p2, c.z, acc);
        acc = fmaf(p3, c.w, acc);
        if (Pb) Pb[e] = make_float4(p0, p1, p2, p3);
    }

    red[tid] = acc;
    __syncthreads();
#pragma unroll
    for (int st = 128; st; st >>= 1) {
        if (tid < st) red[tid] += red[tid + st];
        __syncthreads();
    }
    if (tid == 0) g_part[n * 64 + ib] = red[0];
}

__global__ void costred(float* __restrict__ cost) {
    int n = threadIdx.x;
    if (n < NB) {
        float s = 0.f;
#pragma unroll
        for (int k = 0; k < 64; ++k) s += g_part[n * 64 + k];
        if (cost) cost[n] = s;
        else      g_cost[n] = s;
    }
}

extern "C" void kernel_launch(void* const* d_in, const int* in_sizes, int n_in,
                              void* d_out, int out_size) {
    // C is the largest input; the remaining two are mu, nu in order.
    int ci = 0;
    for (int k = 1; k < n_in; ++k) if (in_sizes[k] > in_sizes[ci]) ci = k;
    const float* in2[2]; int w = 0;
    for (int k = 0; k < n_in && w < 2; ++k) if (k != ci) in2[w++] = (const float*)d_in[k];
    const float* mu = in2[0];
    const float* nu = in2[1];
    const float* C  = (const float*)d_in[ci];

    float* out = (float*)d_out;
    float* cost = nullptr;
    float* pi   = nullptr;
    const int NPI = NB * PP * PP;
    if (out_size >= NPI + NB)      { cost = out;     pi = out + NB; }
    else if (out_size == NPI)      { cost = nullptr; pi = out; }
    else                           { cost = out;     pi = nullptr; }

    init_k<<<(NB * PP + 255) / 256, 256>>>(mu, nu);

    dim3 grid(64, 16);
    colpass<true><<<grid, 256>>>(C);
    rowpass<<<grid, 256>>>(C);
    for (int it = 1; it < 100; ++it) {
        colpass<false><<<grid, 256>>>(C);
        rowpass<<<grid, 256>>>(C);
    }

    finalpass<<<dim3(64, 16), 256>>>(C, pi);
    costred<<<1, 32>>>(cost);
}